// round 14
// baseline (speedup 1.0000x reference)
#include <cuda_runtime.h>
#include <cuda_fp16.h>

// x: (32, 1, 1024, 1024) fp32. out same shape.
#define IMG_N  32
#define HDIM   1024
#define WDIM   1024
#define RSTRIP 16                      // rows per block strip (pass1)
#define STRIPS (HDIM / RSTRIP)         // 64 strips per image
#define NBLOCKS (IMG_N * STRIPS)       // 2048 pass1 blocks
#define RING   6                       // rows in flight (distance-3 pipeline)

// Per-block partial sums (written unconditionally each launch -> no zeroing).
__device__ double g_psum[NBLOCKS];
__device__ double g_pss[NBLOCKS];
// Per-image stats, produced by pass1's last-block reduce.
__device__ float g_mean[IMG_N];
__device__ float g_inv [IMG_N];
// Arrival counters; zero-init at load, self-reset by the reducer each launch.
__device__ unsigned g_done[IMG_N];
// fp16 z scratch (64MB). Static __device__ array = sanctioned scratch path.
__device__ __half g_z[(size_t)IMG_N * HDIM * WDIM];

// ---------------------------------------------------------------- loads/halo
template<bool INTERIOR>
__device__ __forceinline__ void load_row_t(const float* __restrict__ base, int row,
                                           int col, int lane,
                                           float4& v, float& el, float& er) {
    if (!INTERIOR) {
        if (row < 0 || row >= HDIM) {
            v = make_float4(0.f, 0.f, 0.f, 0.f); el = 0.f; er = 0.f; return;
        }
    }
    const float* p = base + (size_t)row * WDIM;
    // Streamed read: x is never re-read; don't displace z in L2.
    v = __ldcs((const float4*)(p + col));
    el = 0.f; er = 0.f;
    if (lane == 0  && col > 0)        el = __ldg(p + col - 1);
    if (lane == 31 && col + 4 < WDIM) er = __ldg(p + col + 4);
}

__device__ __forceinline__ void make_halo(const float4& v, float el, float er,
                                          int lane, float& l, float& r) {
    float lu = __shfl_up_sync(0xffffffffu,  v.w, 1);
    float rd = __shfl_down_sync(0xffffffffu, v.x, 1);
    l = (lane == 0)  ? el : lu;
    r = (lane == 31) ? er : rd;
}

// z = center - (L + 2*DL + 4*D + 8*DR + 16*R + 32*UR + 64*U + 128*UL)/255
// u = row-1, d = row+1 (reference offsets; zero padding outside).
__device__ __forceinline__ void stencil4(const float4& u, float ul, float ur,
                                         const float4& c, float cl, float cr,
                                         const float4& d, float dl, float dr,
                                         float z[4]) {
    const float INV255 = 1.0f / 255.0f;
    z[0] = c.x - (cl  + 2.f*dl  + 4.f*d.x + 8.f*d.y + 16.f*c.y + 32.f*u.y + 64.f*u.x + 128.f*ul ) * INV255;
    z[1] = c.y - (c.x + 2.f*d.x + 4.f*d.y + 8.f*d.z + 16.f*c.z + 32.f*u.z + 64.f*u.y + 128.f*u.x) * INV255;
    z[2] = c.z - (c.y + 2.f*d.y + 4.f*d.z + 8.f*d.w + 16.f*c.w + 32.f*u.w + 64.f*u.z + 128.f*u.y) * INV255;
    z[3] = c.w - (c.z + 2.f*d.z + 4.f*d.w + 8.f*dr  + 16.f*cr  + 32.f*ur  + 64.f*u.w + 128.f*u.z) * INV255;
}

// ============ Pass 1: stencil -> z(fp16) + stats; last block reduces ========
template<bool INTERIOR>
__device__ __forceinline__ void pass1_strip(const float* __restrict__ base,
                                            __half* __restrict__ zb,
                                            int r0, int col, int lane,
                                            float& s, float& ss) {
    float4 v[RING]; float el[RING], er[RING], l[RING], r[RING];
    #pragma unroll
    for (int k = 0; k < RING - 1; k++)            // abs rows r0-1 .. r0+3
        load_row_t<INTERIOR>(base, r0 - 1 + k, col, lane, v[k], el[k], er[k]);
    make_halo(v[0], el[0], er[0], lane, l[0], r[0]);
    make_halo(v[1], el[1], er[1], lane, l[1], r[1]);

    s = 0.f; ss = 0.f;
    #pragma unroll
    for (int i = 0; i < RSTRIP; i++) {
        if (i < RSTRIP - 3) {                     // load abs row r0+i+4
            const int rel = (i + RING - 1) % RING;
            load_row_t<INTERIOR>(base, r0 + i + 4, col, lane, v[rel], el[rel], er[rel]);
        }
        const int a = i % RING, b = (i + 1) % RING, c = (i + 2) % RING;
        make_halo(v[c], el[c], er[c], lane, l[c], r[c]);
        float z[4];
        stencil4(v[a], l[a], r[a], v[b], l[b], r[b], v[c], l[c], r[c], z);
        s  += (z[0] + z[1]) + (z[2] + z[3]);
        ss += (z[0]*z[0] + z[1]*z[1]) + (z[2]*z[2] + z[3]*z[3]);

        // fp16 z store; warp covers full 128B lines -> no read-for-ownership.
        // Default caching: z should LIVE in L2 for pass2.
        __half2 h01 = __floats2half2_rn(z[0], z[1]);
        __half2 h23 = __floats2half2_rn(z[2], z[3]);
        float2 w;
        *reinterpret_cast<__half2*>(&w.x) = h01;
        *reinterpret_cast<__half2*>(&w.y) = h23;
        *(float2*)(zb + (size_t)(r0 + i) * WDIM + col) = w;
    }
}

__global__ void __launch_bounds__(256) ltpe_pass1(const float* __restrict__ x) {
    int strip = blockIdx.x & (STRIPS - 1);
    int img   = blockIdx.x >> 6;
    int r0    = strip * RSTRIP;
    const float* base = x + (size_t)img * HDIM * WDIM;
    __half* zb = g_z + (size_t)img * HDIM * WDIM;
    int col  = threadIdx.x * 4;
    int lane = threadIdx.x & 31;

    float s, ss;
    if (strip != 0 && strip != STRIPS - 1) pass1_strip<true >(base, zb, r0, col, lane, s, ss);
    else                                   pass1_strip<false>(base, zb, r0, col, lane, s, ss);

    #pragma unroll
    for (int o = 16; o > 0; o >>= 1) {
        s  += __shfl_xor_sync(0xffffffffu, s,  o);
        ss += __shfl_xor_sync(0xffffffffu, ss, o);
    }
    __shared__ float ws[8], wss[8];
    int wid = threadIdx.x >> 5;
    if (lane == 0) { ws[wid] = s; wss[wid] = ss; }
    __syncthreads();
    if (threadIdx.x == 0) {
        float S = 0.f, SS = 0.f;
        #pragma unroll
        for (int i = 0; i < 8; i++) { S += ws[i]; SS += wss[i]; }
        g_psum[blockIdx.x] = (double)S;
        g_pss [blockIdx.x] = (double)SS;
    }

    // ---- last-block-per-image stats reduce (spin-free, deterministic) ----
    __shared__ bool amLast;
    if (threadIdx.x == 0) {
        __threadfence();                            // release my partial
        unsigned prev = atomicAdd(&g_done[img], 1u);
        amLast = (prev == STRIPS - 1);
    }
    __syncthreads();
    if (amLast) {
        __shared__ double rs[STRIPS], rss[STRIPS];
        if (threadIdx.x == 0) __threadfence();      // acquire others' partials
        __syncthreads();
        if (threadIdx.x < STRIPS) {
            // L2-coherent loads (bypass L1; other SMs wrote these).
            rs [threadIdx.x] = __ldcg(&g_psum[img * STRIPS + threadIdx.x]);
            rss[threadIdx.x] = __ldcg(&g_pss [img * STRIPS + threadIdx.x]);
        }
        __syncthreads();
        #pragma unroll
        for (int o = STRIPS / 2; o > 0; o >>= 1) {
            if (threadIdx.x < o) {
                rs [threadIdx.x] += rs [threadIdx.x + o];
                rss[threadIdx.x] += rss[threadIdx.x + o];
            }
            __syncthreads();
        }
        if (threadIdx.x == 0) {
            const double N = (double)HDIM * WDIM;
            double mm  = rs[0] / N;
            double var = rss[0] / N - mm * mm;
            g_mean[img] = (float)mm;
            // o = 0.5*z + 0.5 with IN eps=1e-5 => normalize z with eps' = 4e-5
            g_inv [img] = (float)rsqrt(var + 4e-5);
            g_done[img] = 0u;                       // self-reset for next launch
        }
    }
}

// ============ Pass 2: pure streaming normalize (no reduce, tiny regs) =======
// 16 halfs per thread: 2 x 16B z loads -> 4 x 16B out stores.
#define P2_TPB    256
#define P2_CHUNK  (P2_TPB * 16)                    // 4096 halfs per block
#define P2_BLOCKS ((IMG_N * HDIM * WDIM) / P2_CHUNK)  // 8192

__global__ void __launch_bounds__(P2_TPB) ltpe_pass2(float* __restrict__ out) {
    // Reverse order: read the most-recently-written z first (LRU-friendly).
    size_t b    = (size_t)(P2_BLOCKS - 1) - blockIdx.x;
    size_t base = b * P2_CHUNK + (size_t)threadIdx.x * 8;
    int img     = (int)(base >> 20);               // 1M elements per image

    // Issue both z loads first (MLP), then the broadcast stats loads.
    float4 z0 = __ldlu((const float4*)(g_z + base));
    float4 z1 = __ldlu((const float4*)(g_z + base + (size_t)P2_TPB * 8));
    float m   = __ldg(&g_mean[img]);
    float inv = __ldg(&g_inv [img]);

    const __half2* h0 = reinterpret_cast<const __half2*>(&z0);
    const __half2* h1 = reinterpret_cast<const __half2*>(&z1);

    #pragma unroll
    for (int u = 0; u < 2; u++) {
        const __half2* h = (u == 0) ? h0 : h1;
        size_t off = base + (size_t)u * P2_TPB * 8;
        float2 fa = __half22float2(h[0]);
        float2 fb = __half22float2(h[1]);
        float2 fc = __half22float2(h[2]);
        float2 fd = __half22float2(h[3]);
        float4 oa, ob;
        oa.x = (fa.x - m) * inv;  oa.y = (fa.y - m) * inv;
        oa.z = (fb.x - m) * inv;  oa.w = (fb.y - m) * inv;
        ob.x = (fc.x - m) * inv;  ob.y = (fc.y - m) * inv;
        ob.z = (fd.x - m) * inv;  ob.w = (fd.y - m) * inv;
        __stcs((float4*)(out + off),     oa);
        __stcs((float4*)(out + off + 4), ob);
    }
}

extern "C" void kernel_launch(void* const* d_in, const int* in_sizes, int n_in,
                              void* d_out, int out_size) {
    const float* x   = (const float*)d_in[0];
    float*       out = (float*)d_out;

    ltpe_pass1<<<NBLOCKS, 256>>>(x);
    ltpe_pass2<<<P2_BLOCKS, P2_TPB>>>(out);
}

// round 15
// speedup vs baseline: 1.1147x; 1.1147x over previous
#include <cuda_runtime.h>
#include <cuda_fp16.h>

// x: (32, 1, 1024, 1024) fp32. out same shape.
#define IMG_N  32
#define HDIM   1024
#define WDIM   1024
#define RSTRIP 16                      // rows per block strip
#define STRIPS (HDIM / RSTRIP)         // 64 strips per image
#define NBLOCKS (IMG_N * STRIPS)       // 2048 blocks per pass
#define RING   6                       // rows in flight (distance-3 pipeline)

// Per-block partial sums (written unconditionally each launch -> no zeroing).
__device__ double g_psum[NBLOCKS];
__device__ double g_pss[NBLOCKS];
// Per-image stats, produced by the tiny mid kernel.
__device__ float g_mean[IMG_N];
__device__ float g_inv [IMG_N];
// fp16 z scratch (64MB). Static __device__ array = sanctioned scratch path.
__device__ __half g_z[(size_t)IMG_N * HDIM * WDIM];

// ---------------------------------------------------------------- loads/halo
template<bool INTERIOR>
__device__ __forceinline__ void load_row_t(const float* __restrict__ base, int row,
                                           int col, int lane,
                                           float4& v, float& el, float& er) {
    if (!INTERIOR) {
        if (row < 0 || row >= HDIM) {
            v = make_float4(0.f, 0.f, 0.f, 0.f); el = 0.f; er = 0.f; return;
        }
    }
    const float* p = base + (size_t)row * WDIM;
    // Streamed read: x is never re-read; don't displace z in L2.
    v = __ldcs((const float4*)(p + col));
    el = 0.f; er = 0.f;
    if (lane == 0  && col > 0)        el = __ldg(p + col - 1);
    if (lane == 31 && col + 4 < WDIM) er = __ldg(p + col + 4);
}

__device__ __forceinline__ void make_halo(const float4& v, float el, float er,
                                          int lane, float& l, float& r) {
    float lu = __shfl_up_sync(0xffffffffu,  v.w, 1);
    float rd = __shfl_down_sync(0xffffffffu, v.x, 1);
    l = (lane == 0)  ? el : lu;
    r = (lane == 31) ? er : rd;
}

// z = center - (L + 2*DL + 4*D + 8*DR + 16*R + 32*UR + 64*U + 128*UL)/255
// u = row-1, d = row+1 (reference offsets; zero padding outside).
__device__ __forceinline__ void stencil4(const float4& u, float ul, float ur,
                                         const float4& c, float cl, float cr,
                                         const float4& d, float dl, float dr,
                                         float z[4]) {
    const float INV255 = 1.0f / 255.0f;
    z[0] = c.x - (cl  + 2.f*dl  + 4.f*d.x + 8.f*d.y + 16.f*c.y + 32.f*u.y + 64.f*u.x + 128.f*ul ) * INV255;
    z[1] = c.y - (c.x + 2.f*d.x + 4.f*d.y + 8.f*d.z + 16.f*c.z + 32.f*u.z + 64.f*u.y + 128.f*u.x) * INV255;
    z[2] = c.z - (c.y + 2.f*d.y + 4.f*d.z + 8.f*d.w + 16.f*c.w + 32.f*u.w + 64.f*u.z + 128.f*u.y) * INV255;
    z[3] = c.w - (c.z + 2.f*d.z + 4.f*d.w + 8.f*dr  + 16.f*cr  + 32.f*ur  + 64.f*u.w + 128.f*u.z) * INV255;
}

// ============ Pass 1: stencil -> z(fp16) + per-block stats (R13 body) ========
template<bool INTERIOR>
__device__ __forceinline__ void pass1_strip(const float* __restrict__ base,
                                            __half* __restrict__ zb,
                                            int r0, int col, int lane,
                                            float& s, float& ss) {
    float4 v[RING]; float el[RING], er[RING], l[RING], r[RING];
    #pragma unroll
    for (int k = 0; k < RING - 1; k++)            // abs rows r0-1 .. r0+3
        load_row_t<INTERIOR>(base, r0 - 1 + k, col, lane, v[k], el[k], er[k]);
    make_halo(v[0], el[0], er[0], lane, l[0], r[0]);
    make_halo(v[1], el[1], er[1], lane, l[1], r[1]);

    s = 0.f; ss = 0.f;
    #pragma unroll
    for (int i = 0; i < RSTRIP; i++) {
        if (i < RSTRIP - 3) {                     // load abs row r0+i+4
            const int rel = (i + RING - 1) % RING;
            load_row_t<INTERIOR>(base, r0 + i + 4, col, lane, v[rel], el[rel], er[rel]);
        }
        const int a = i % RING, b = (i + 1) % RING, c = (i + 2) % RING;
        make_halo(v[c], el[c], er[c], lane, l[c], r[c]);
        float z[4];
        stencil4(v[a], l[a], r[a], v[b], l[b], r[b], v[c], l[c], r[c], z);
        s  += (z[0] + z[1]) + (z[2] + z[3]);
        ss += (z[0]*z[0] + z[1]*z[1]) + (z[2]*z[2] + z[3]*z[3]);

        // fp16 z store; warp covers full 128B lines -> no read-for-ownership.
        // Default caching: z should LIVE in L2 for pass2.
        __half2 h01 = __floats2half2_rn(z[0], z[1]);
        __half2 h23 = __floats2half2_rn(z[2], z[3]);
        float2 w;
        *reinterpret_cast<__half2*>(&w.x) = h01;
        *reinterpret_cast<__half2*>(&w.y) = h23;
        *(float2*)(zb + (size_t)(r0 + i) * WDIM + col) = w;
    }
}

__global__ void __launch_bounds__(256) ltpe_pass1(const float* __restrict__ x) {
    int strip = blockIdx.x & (STRIPS - 1);
    int img   = blockIdx.x >> 6;
    int r0    = strip * RSTRIP;
    const float* base = x + (size_t)img * HDIM * WDIM;
    __half* zb = g_z + (size_t)img * HDIM * WDIM;
    int col  = threadIdx.x * 4;
    int lane = threadIdx.x & 31;

    float s, ss;
    if (strip != 0 && strip != STRIPS - 1) pass1_strip<true >(base, zb, r0, col, lane, s, ss);
    else                                   pass1_strip<false>(base, zb, r0, col, lane, s, ss);

    #pragma unroll
    for (int o = 16; o > 0; o >>= 1) {
        s  += __shfl_xor_sync(0xffffffffu, s,  o);
        ss += __shfl_xor_sync(0xffffffffu, ss, o);
    }
    __shared__ float ws[8], wss[8];
    int wid = threadIdx.x >> 5;
    if (lane == 0) { ws[wid] = s; wss[wid] = ss; }
    __syncthreads();
    if (threadIdx.x == 0) {
        float S = 0.f, SS = 0.f;
        #pragma unroll
        for (int i = 0; i < 8; i++) { S += ws[i]; SS += wss[i]; }
        g_psum[blockIdx.x] = (double)S;
        g_pss [blockIdx.x] = (double)SS;
    }
}

// ============ Mid: per-image stats reduce (32 blocks x 64 threads) ==========
__global__ void __launch_bounds__(64) ltpe_stats() {
    int img = blockIdx.x;
    __shared__ double rs[STRIPS], rss[STRIPS];
    rs [threadIdx.x] = g_psum[img * STRIPS + threadIdx.x];
    rss[threadIdx.x] = g_pss [img * STRIPS + threadIdx.x];
    __syncthreads();
    #pragma unroll
    for (int o = STRIPS / 2; o > 0; o >>= 1) {
        if (threadIdx.x < o) {
            rs [threadIdx.x] += rs [threadIdx.x + o];
            rss[threadIdx.x] += rss[threadIdx.x + o];
        }
        __syncthreads();
    }
    if (threadIdx.x == 0) {
        const double N = (double)HDIM * WDIM;
        double mm  = rs[0] / N;
        double var = rss[0] / N - mm * mm;
        g_mean[img] = (float)mm;
        // o = 0.5*z + 0.5 with IN eps=1e-5 => normalize z with eps' = 4e-5
        g_inv [img] = (float)rsqrt(var + 4e-5);
    }
}

// ============ Pass 2: pure streaming normalize (R13 strip layout) ===========
__global__ void __launch_bounds__(256) ltpe_pass2(float* __restrict__ out) {
    // Reverse order: read the most-recently-written z first (LRU-friendly).
    int bid   = (NBLOCKS - 1) - blockIdx.x;
    int strip = bid & (STRIPS - 1);
    int img   = bid >> 6;
    int r0    = strip * RSTRIP;
    int col   = threadIdx.x * 4;

    const __half* zb = g_z + (size_t)img * HDIM * WDIM;
    float* obase = out + (size_t)img * HDIM * WDIM;

    const float m   = __ldg(&g_mean[img]);
    const float inv = __ldg(&g_inv [img]);

    #pragma unroll
    for (int i = 0; i < RSTRIP; i++) {
        float2 zr = __ldlu((const float2*)(zb + (size_t)(r0 + i) * WDIM + col));
        __half2 h01 = *reinterpret_cast<__half2*>(&zr.x);
        __half2 h23 = *reinterpret_cast<__half2*>(&zr.y);
        float2 f01 = __half22float2(h01);
        float2 f23 = __half22float2(h23);
        float4 o4;
        o4.x = (f01.x - m) * inv;
        o4.y = (f01.y - m) * inv;
        o4.z = (f23.x - m) * inv;
        o4.w = (f23.y - m) * inv;
        // Evict-first: output never re-read; don't displace z in L2.
        __stcs((float4*)(obase + (size_t)(r0 + i) * WDIM + col), o4);
    }
}

extern "C" void kernel_launch(void* const* d_in, const int* in_sizes, int n_in,
                              void* d_out, int out_size) {
    const float* x   = (const float*)d_in[0];
    float*       out = (float*)d_out;

    ltpe_pass1<<<NBLOCKS, 256>>>(x);
    ltpe_stats<<<IMG_N, STRIPS>>>();
    ltpe_pass2<<<NBLOCKS, 256>>>(out);
}

// round 17
// speedup vs baseline: 1.1873x; 1.0651x over previous
#include <cuda_runtime.h>
#include <cuda_fp16.h>

// x: (32, 1, 1024, 1024) fp32. out same shape.
#define IMG_N  32
#define HDIM   1024
#define WDIM   1024
#define RSTRIP 16                      // rows per block strip
#define STRIPS (HDIM / RSTRIP)         // 64 strips per image
#define NBLOCKS (IMG_N * STRIPS)       // 2048 blocks per pass
#define RING   6                       // rows in flight (distance-3 pipeline)

// Per-block partial sums (written unconditionally each launch -> no zeroing).
__device__ double g_psum[NBLOCKS];
__device__ double g_pss[NBLOCKS];
// Per-image stats, produced by the tiny mid kernel.
__device__ float g_mean[IMG_N];
__device__ float g_inv [IMG_N];
// fp16 z scratch (64MB). Static __device__ array = sanctioned scratch path.
__device__ __half g_z[(size_t)IMG_N * HDIM * WDIM];

// ---------------------------------------------------------------- loads/halo
template<bool INTERIOR>
__device__ __forceinline__ void load_row_t(const float* __restrict__ base, int row,
                                           int col, int lane,
                                           float4& v, float& el, float& er) {
    if (!INTERIOR) {
        if (row < 0 || row >= HDIM) {
            v = make_float4(0.f, 0.f, 0.f, 0.f); el = 0.f; er = 0.f; return;
        }
    }
    const float* p = base + (size_t)row * WDIM;
    // Streamed read: x is never re-read; don't displace z in L2.
    v = __ldcs((const float4*)(p + col));
    el = 0.f; er = 0.f;
    if (lane == 0  && col > 0)        el = __ldg(p + col - 1);
    if (lane == 31 && col + 4 < WDIM) er = __ldg(p + col + 4);
}

__device__ __forceinline__ void make_halo(const float4& v, float el, float er,
                                          int lane, float& l, float& r) {
    float lu = __shfl_up_sync(0xffffffffu,  v.w, 1);
    float rd = __shfl_down_sync(0xffffffffu, v.x, 1);
    l = (lane == 0)  ? el : lu;
    r = (lane == 31) ? er : rd;
}

// z = center - (L + 2*DL + 4*D + 8*DR + 16*R + 32*UR + 64*U + 128*UL)/255
// u = row-1, d = row+1 (reference offsets; zero padding outside).
__device__ __forceinline__ void stencil4(const float4& u, float ul, float ur,
                                         const float4& c, float cl, float cr,
                                         const float4& d, float dl, float dr,
                                         float z[4]) {
    const float INV255 = 1.0f / 255.0f;
    z[0] = c.x - (cl  + 2.f*dl  + 4.f*d.x + 8.f*d.y + 16.f*c.y + 32.f*u.y + 64.f*u.x + 128.f*ul ) * INV255;
    z[1] = c.y - (c.x + 2.f*d.x + 4.f*d.y + 8.f*d.z + 16.f*c.z + 32.f*u.z + 64.f*u.y + 128.f*u.x) * INV255;
    z[2] = c.z - (c.y + 2.f*d.y + 4.f*d.z + 8.f*d.w + 16.f*c.w + 32.f*u.w + 64.f*u.z + 128.f*u.y) * INV255;
    z[3] = c.w - (c.z + 2.f*d.z + 4.f*d.w + 8.f*dr  + 16.f*cr  + 32.f*ur  + 64.f*u.w + 128.f*u.z) * INV255;
}

// ============ Pass 1: stencil -> z(fp16) + per-block stats (R13 body) ========
template<bool INTERIOR>
__device__ __forceinline__ void pass1_strip(const float* __restrict__ base,
                                            __half* __restrict__ zb,
                                            int r0, int col, int lane,
                                            float& s, float& ss) {
    float4 v[RING]; float el[RING], er[RING], l[RING], r[RING];
    #pragma unroll
    for (int k = 0; k < RING - 1; k++)            // abs rows r0-1 .. r0+3
        load_row_t<INTERIOR>(base, r0 - 1 + k, col, lane, v[k], el[k], er[k]);
    make_halo(v[0], el[0], er[0], lane, l[0], r[0]);
    make_halo(v[1], el[1], er[1], lane, l[1], r[1]);

    s = 0.f; ss = 0.f;
    #pragma unroll
    for (int i = 0; i < RSTRIP; i++) {
        if (i < RSTRIP - 3) {                     // load abs row r0+i+4
            const int rel = (i + RING - 1) % RING;
            load_row_t<INTERIOR>(base, r0 + i + 4, col, lane, v[rel], el[rel], er[rel]);
        }
        const int a = i % RING, b = (i + 1) % RING, c = (i + 2) % RING;
        make_halo(v[c], el[c], er[c], lane, l[c], r[c]);
        float z[4];
        stencil4(v[a], l[a], r[a], v[b], l[b], r[b], v[c], l[c], r[c], z);
        s  += (z[0] + z[1]) + (z[2] + z[3]);
        ss += (z[0]*z[0] + z[1]*z[1]) + (z[2]*z[2] + z[3]*z[3]);

        // fp16 z store; warp covers full 128B lines -> no read-for-ownership.
        // Default caching: z should LIVE in L2 for pass2.
        __half2 h01 = __floats2half2_rn(z[0], z[1]);
        __half2 h23 = __floats2half2_rn(z[2], z[3]);
        float2 w;
        *reinterpret_cast<__half2*>(&w.x) = h01;
        *reinterpret_cast<__half2*>(&w.y) = h23;
        *(float2*)(zb + (size_t)(r0 + i) * WDIM + col) = w;
    }
}

__global__ void __launch_bounds__(256) ltpe_pass1(const float* __restrict__ x) {
    int strip = blockIdx.x & (STRIPS - 1);
    int img   = blockIdx.x >> 6;
    int r0    = strip * RSTRIP;
    const float* base = x + (size_t)img * HDIM * WDIM;
    __half* zb = g_z + (size_t)img * HDIM * WDIM;
    int col  = threadIdx.x * 4;
    int lane = threadIdx.x & 31;

    float s, ss;
    if (strip != 0 && strip != STRIPS - 1) pass1_strip<true >(base, zb, r0, col, lane, s, ss);
    else                                   pass1_strip<false>(base, zb, r0, col, lane, s, ss);

    #pragma unroll
    for (int o = 16; o > 0; o >>= 1) {
        s  += __shfl_xor_sync(0xffffffffu, s,  o);
        ss += __shfl_xor_sync(0xffffffffu, ss, o);
    }
    __shared__ float ws[8], wss[8];
    int wid = threadIdx.x >> 5;
    if (lane == 0) { ws[wid] = s; wss[wid] = ss; }
    __syncthreads();
    if (threadIdx.x == 0) {
        float S = 0.f, SS = 0.f;
        #pragma unroll
        for (int i = 0; i < 8; i++) { S += ws[i]; SS += wss[i]; }
        g_psum[blockIdx.x] = (double)S;
        g_pss [blockIdx.x] = (double)SS;
    }
}

// ============ Mid: per-image stats reduce (32 blocks x 64 threads) ==========
__global__ void __launch_bounds__(64) ltpe_stats() {
    int img = blockIdx.x;
    __shared__ double rs[STRIPS], rss[STRIPS];
    rs [threadIdx.x] = g_psum[img * STRIPS + threadIdx.x];
    rss[threadIdx.x] = g_pss [img * STRIPS + threadIdx.x];
    __syncthreads();
    #pragma unroll
    for (int o = STRIPS / 2; o > 0; o >>= 1) {
        if (threadIdx.x < o) {
            rs [threadIdx.x] += rs [threadIdx.x + o];
            rss[threadIdx.x] += rss[threadIdx.x + o];
        }
        __syncthreads();
    }
    if (threadIdx.x == 0) {
        const double N = (double)HDIM * WDIM;
        double mm  = rs[0] / N;
        double var = rss[0] / N - mm * mm;
        g_mean[img] = (float)mm;
        // o = 0.5*z + 0.5 with IN eps=1e-5 => normalize z with eps' = 4e-5
        g_inv [img] = (float)rsqrt(var + 4e-5);
    }
}

// ============ Pass 2: deep-prefetch streaming normalize =====================
// R13's pass2 structure (16 outstanding z loads per thread = the MLP source)
// with the smem reduce deleted — stats come from the mid kernel via __ldg.
__global__ void __launch_bounds__(256) ltpe_pass2(float* __restrict__ out) {
    // Reverse order: read the most-recently-written z first (LRU-friendly).
    int bid   = (NBLOCKS - 1) - blockIdx.x;
    int strip = bid & (STRIPS - 1);
    int img   = bid >> 6;
    int r0    = strip * RSTRIP;
    int col   = threadIdx.x * 4;

    const __half* zb = g_z + (size_t)img * HDIM * WDIM;

    // Issue ALL 16 z loads first: 16 outstanding loads/thread.
    float2 zraw[RSTRIP];
    #pragma unroll
    for (int i = 0; i < RSTRIP; i++)
        zraw[i] = __ldlu((const float2*)(zb + (size_t)(r0 + i) * WDIM + col));

    const float m   = __ldg(&g_mean[img]);
    const float inv = __ldg(&g_inv [img]);

    float* obase = out + (size_t)img * HDIM * WDIM;
    #pragma unroll
    for (int i = 0; i < RSTRIP; i++) {
        __half2 h01 = *reinterpret_cast<__half2*>(&zraw[i].x);
        __half2 h23 = *reinterpret_cast<__half2*>(&zraw[i].y);
        float2 f01 = __half22float2(h01);
        float2 f23 = __half22float2(h23);
        float4 o4;
        o4.x = (f01.x - m) * inv;
        o4.y = (f01.y - m) * inv;
        o4.z = (f23.x - m) * inv;
        o4.w = (f23.y - m) * inv;
        // Evict-first: output never re-read; don't displace z in L2.
        __stcs((float4*)(obase + (size_t)(r0 + i) * WDIM + col), o4);
    }
}

extern "C" void kernel_launch(void* const* d_in, const int* in_sizes, int n_in,
                              void* d_out, int out_size) {
    const float* x   = (const float*)d_in[0];
    float*       out = (float*)d_out;

    ltpe_pass1<<<NBLOCKS, 256>>>(x);
    ltpe_stats<<<IMG_N, STRIPS>>>();
    ltpe_pass2<<<NBLOCKS, 256>>>(out);
}